// round 13
// baseline (speedup 1.0000x reference)
#include <cuda_runtime.h>
#include <cuda_fp16.h>
#include <cstdint>

#define B_DIM 4
#define C_DIM 128
#define L_DIM 24
#define HW_DIM 4096

#define SK   136          // fp16 row stride in elements
#define ROWB (SK * 2)     // 272 bytes/row

#define SM_M  0
#define SM_W  34816
#define SM_H0 69632
#define SM_H1 104448
#define SM_X0 139264
#define SM_X1 174080
#define SMEM_BYTES 208896

#define NTHREADS 512

__device__ __align__(16) float g_M[C_DIM * C_DIM];             // (U@V)[c][k]
__device__ __align__(16) float g_decay[B_DIM * L_DIM * C_DIM]; // exp(-softplus(lam)*dt)

// ---------------- helpers ----------------
__device__ __forceinline__ uint32_t smem_u32(const void* p) {
    uint32_t a;
    asm("{ .reg .u64 t; cvta.to.shared.u64 t, %1; cvt.u32.u64 %0, t; }" : "=r"(a) : "l"(p));
    return a;
}
__device__ __forceinline__ void ldsm4(uint32_t* r, uint32_t a) {
    asm volatile("ldmatrix.sync.aligned.m8n8.x4.shared.b16 {%0,%1,%2,%3}, [%4];"
                 : "=r"(r[0]), "=r"(r[1]), "=r"(r[2]), "=r"(r[3]) : "r"(a));
}
__device__ __forceinline__ void ldsm4t(uint32_t* r, uint32_t a) {
    asm volatile("ldmatrix.sync.aligned.m8n8.x4.trans.shared.b16 {%0,%1,%2,%3}, [%4];"
                 : "=r"(r[0]), "=r"(r[1]), "=r"(r[2]), "=r"(r[3]) : "r"(a));
}
__device__ __forceinline__ void mma16816(float* d, const uint32_t* a, const uint32_t* b) {
    asm volatile("mma.sync.aligned.m16n8k16.row.col.f32.f16.f16.f32 "
                 "{%0,%1,%2,%3}, {%4,%5,%6,%7}, {%8,%9}, {%0,%1,%2,%3};"
                 : "+f"(d[0]), "+f"(d[1]), "+f"(d[2]), "+f"(d[3])
                 : "r"(a[0]), "r"(a[1]), "r"(a[2]), "r"(a[3]), "r"(b[0]), "r"(b[1]));
}
__device__ __forceinline__ uint32_t pack_h2(float x0, float x1) {
    uint32_t r;
    asm("cvt.rn.f16x2.f32 %0, %1, %2;" : "=r"(r) : "f"(x1), "f"(x0));
    return r;
}
__device__ __forceinline__ float2 unpack_h2(uint32_t v) {
    return __half22float2(*reinterpret_cast<__half2*>(&v));
}

// ---------------- precompute ----------------
__global__ void precompute_kernel(const float* __restrict__ lam,
                                  const float* __restrict__ U,
                                  const float* __restrict__ V,
                                  const float* __restrict__ listT) {
    int tid = threadIdx.x;
    if (blockIdx.x < 64) {
        int e = blockIdx.x * 256 + tid;
        int c = e >> 7, k = e & 127;
        float s0 = 0.f, s1 = 0.f;
        #pragma unroll 8
        for (int r = 0; r < 64; r += 2) {
            s0 += U[c * 64 + r] * V[r * C_DIM + k];
            s1 += U[c * 64 + r + 1] * V[(r + 1) * C_DIM + k];
        }
        g_M[e] = s0 + s1;
    } else {
        int idx = (blockIdx.x - 64) * 256 + tid;
        if (idx < B_DIM * L_DIM * C_DIM) {
            int c = idx & 127;
            int t = (idx >> 7) % L_DIM;
            int b = idx / (L_DIM * C_DIM);
            float sp = log1pf(expf(lam[c]));
            g_decay[idx] = expf(-sp * listT[b * L_DIM + t]);
        }
    }
}

// single-pass fp16 GEMM, k=128: acc[2][4][4] += A[m0..+32][k] * B[k][n0..+32]
__device__ __forceinline__ void gemm128(uint32_t aB, uint32_t bB,
                                        int m0, int n0, int lane,
                                        float acc[2][4][4]) {
    const int arow = lane & 15;
    const int aq   = lane >> 4;
    #pragma unroll
    for (int k = 0; k < 128; k += 16) {
        uint32_t ah[2][4];
        #pragma unroll
        for (int mt = 0; mt < 2; ++mt) {
            uint32_t addr = aB + (uint32_t)((m0 + mt * 16 + arow) * ROWB + k * 2 + aq * 16);
            ldsm4(ah[mt], addr);
        }
        #pragma unroll
        for (int ng = 0; ng < 2; ++ng) {
            uint32_t addr = bB + (uint32_t)((k + arow) * ROWB + (n0 + ng * 16) * 2 + aq * 16);
            uint32_t bv[4];
            ldsm4t(bv, addr);
            #pragma unroll
            for (int hh = 0; hh < 2; ++hh) {
                const int nt = ng * 2 + hh;
                mma16816(acc[0][nt], ah[0], bv + hh * 2);
                mma16816(acc[1][nt], ah[1], bv + hh * 2);
            }
        }
    }
}

// ---------------- main kernel ----------------
__global__ __launch_bounds__(NTHREADS, 1)
void recurrent_kernel(const float* __restrict__ x,
                      const float* __restrict__ h0,
                      const float* __restrict__ Wout,
                      float* __restrict__ out,
                      float* __restrict__ hfin) {
    extern __shared__ char smem[];
    const uint32_t sb = smem_u32(smem);

    const int tid  = threadIdx.x;
    const int lane = tid & 31;
    const int wid  = tid >> 5;            // 0..15
    const int b    = blockIdx.x >> 5;
    const int s0   = (blockIdx.x & 31) * 128;
    const int wm   = wid & 3;
    const int wn   = wid >> 2;
    const int m0   = wm * 32;
    const int n0   = wn * 32;
    const int g    = lane >> 2;
    const int tq   = lane & 3;
    const size_t rstride = (size_t)L_DIM * HW_DIM;

    const int sr  = tid >> 5;       // staging base row (stride 16)
    const int sc4 = tid & 31;       // float4 column

    // ---- stationary weights (fp16) ----
    for (int e = tid; e < C_DIM * C_DIM; e += NTHREADS) {
        int r = e >> 7, k = e & 127;
        uint32_t off = (uint32_t)(r * ROWB + k * 2);
        *(__half*)(smem + SM_M + off) = __float2half_rn(g_M[e]);
        *(__half*)(smem + SM_W + off) = __float2half_rn(Wout[e]);
    }

    // ---- initial hidden state fragments ----
    float h[2][4][4];
    #pragma unroll
    for (int mt = 0; mt < 2; ++mt) {
        #pragma unroll
        for (int nt = 0; nt < 4; ++nt) {
            int c_lo = m0 + mt * 16 + g;
            int s    = s0 + n0 + nt * 8 + tq * 2;
            float2 v0 = *(const float2*)&h0[(size_t)(b * C_DIM + c_lo) * HW_DIM + s];
            float2 v1 = *(const float2*)&h0[(size_t)(b * C_DIM + c_lo + 8) * HW_DIM + s];
            h[mt][nt][0] = v0.x; h[mt][nt][1] = v0.y;
            h[mt][nt][2] = v1.x; h[mt][nt][3] = v1.y;
        }
    }

    // ---- stage x(0) -> X0 directly; prefetch x(1) -> xr ----
    #pragma unroll
    for (int it = 0; it < 8; ++it) {
        int r = it * 16 + sr;
        float4 v = *(const float4*)(x + ((size_t)(b * C_DIM + r) * L_DIM + 0) * HW_DIM
                                      + s0 + sc4 * 4);
        *(uint2*)(smem + SM_X0 + (uint32_t)(r * ROWB + sc4 * 8)) =
            make_uint2(pack_h2(v.x, v.y), pack_h2(v.z, v.w));
    }
    float4 xr[8];
    #pragma unroll
    for (int it = 0; it < 8; ++it) {
        int r = it * 16 + sr;
        xr[it] = *(const float4*)(x + ((size_t)(b * C_DIM + r) * L_DIM + 1) * HW_DIM
                                    + s0 + sc4 * 4);
    }
    __syncthreads();   // weights + X0 visible

    float accR[2][4][4];   // residual + gemm2 accumulator, carried across regions
    {
        // ---- preamble region: gemm1(x(0)) -> rec -> h(0); prep t=0 ----
        float accU[2][4][4];
        #pragma unroll
        for (int mt = 0; mt < 2; ++mt)
            #pragma unroll
            for (int nt = 0; nt < 4; ++nt)
                #pragma unroll
                for (int q = 0; q < 4; ++q) accU[mt][nt][q] = 0.f;
        gemm128(sb + SM_M, sb + SM_X0, m0, n0, lane, accU);

        const float* dk = &g_decay[(b * L_DIM + 0) * C_DIM];
        #pragma unroll
        for (int mt = 0; mt < 2; ++mt) {
            float dA = __ldg(&dk[m0 + mt * 16 + g]);
            float dB = __ldg(&dk[m0 + mt * 16 + 8 + g]);
            #pragma unroll
            for (int nt = 0; nt < 4; ++nt) {
                h[mt][nt][0] = dA * h[mt][nt][0] + accU[mt][nt][0];
                h[mt][nt][1] = dA * h[mt][nt][1] + accU[mt][nt][1];
                h[mt][nt][2] = dB * h[mt][nt][2] + accU[mt][nt][2];
                h[mt][nt][3] = dB * h[mt][nt][3] + accU[mt][nt][3];
            }
        }
        // h-write h(0) -> H0
        #pragma unroll
        for (int mt = 0; mt < 2; ++mt)
            #pragma unroll
            for (int nt = 0; nt < 4; ++nt) {
                int c_lo = m0 + mt * 16 + g;
                int cb   = (n0 + nt * 8 + tq * 2) * 2;
                *(uint32_t*)(smem + SM_H0 + (uint32_t)(c_lo * ROWB + cb)) =
                    pack_h2(h[mt][nt][0], h[mt][nt][1]);
                *(uint32_t*)(smem + SM_H0 + (uint32_t)((c_lo + 8) * ROWB + cb)) =
                    pack_h2(h[mt][nt][2], h[mt][nt][3]);
            }
        // residual accR = x(0) from X0
        #pragma unroll
        for (int mt = 0; mt < 2; ++mt)
            #pragma unroll
            for (int nt = 0; nt < 4; ++nt) {
                int c_lo = m0 + mt * 16 + g;
                int cb   = (n0 + nt * 8 + tq * 2) * 2;
                float2 r0 = unpack_h2(*(const uint32_t*)(smem + SM_X0 + (uint32_t)(c_lo * ROWB + cb)));
                float2 r1 = unpack_h2(*(const uint32_t*)(smem + SM_X0 + (uint32_t)((c_lo + 8) * ROWB + cb)));
                accR[mt][nt][0] = r0.x; accR[mt][nt][1] = r0.y;
                accR[mt][nt][2] = r1.x; accR[mt][nt][3] = r1.y;
            }
        // stage x(1) -> X1; prefetch x(2)
        #pragma unroll
        for (int it = 0; it < 8; ++it) {
            int r = it * 16 + sr;
            float4 v = xr[it];
            *(uint2*)(smem + SM_X1 + (uint32_t)(r * ROWB + sc4 * 8)) =
                make_uint2(pack_h2(v.x, v.y), pack_h2(v.z, v.w));
        }
        #pragma unroll
        for (int it = 0; it < 8; ++it) {
            int r = it * 16 + sr;
            xr[it] = *(const float4*)(x + ((size_t)(b * C_DIM + r) * L_DIM + 2) * HW_DIM
                                        + s0 + sc4 * 4);
        }
        __syncthreads();
    }

    // ---- main regions: ONE barrier per step ----
    for (int t = 0; t < L_DIM - 1; ++t) {
        const uint32_t hcur = sb + (uint32_t)((t & 1) ? SM_H1 : SM_H0);
        const uint32_t hnxt = sb + (uint32_t)((t & 1) ? SM_H0 : SM_H1);
        const uint32_t xnxt = sb + (uint32_t)((t & 1) ? SM_X0 : SM_X1);   // x(t+1)
        const uint32_t xstg = sb + (uint32_t)((t & 1) ? SM_X1 : SM_X0);   // dest for x(t+2)

        // ---- GEMM2: out(t) = x(t) + W @ h(t) ----
        gemm128(sb + SM_W, hcur, m0, n0, lane, accR);
        #pragma unroll
        for (int mt = 0; mt < 2; ++mt)
            #pragma unroll
            for (int nt = 0; nt < 4; ++nt) {
                int d_lo = m0 + mt * 16 + g;
                float* po = out + ((size_t)(b * C_DIM + d_lo) * L_DIM + t) * HW_DIM
                                + s0 + n0 + nt * 8 + tq * 2;
                *(float2*)po = make_float2(accR[mt][nt][0], accR[mt][nt][1]);
                *(float2*)(po + 8 * rstride) = make_float2(accR[mt][nt][2], accR[mt][nt][3]);
            }

        // ---- GEMM1: u(t+1) = M @ x(t+1) ----
        float accU[2][4][4];
        #pragma unroll
        for (int mt = 0; mt < 2; ++mt)
            #pragma unroll
            for (int nt = 0; nt < 4; ++nt)
                #pragma unroll
                for (int q = 0; q < 4; ++q) accU[mt][nt][q] = 0.f;
        gemm128(sb + SM_M, xnxt, m0, n0, lane, accU);

        // ---- rec: h(t+1) = d(t+1)*h(t) + u(t+1) ----
        {
            const float* dk = &g_decay[(b * L_DIM + t + 1) * C_DIM];
            #pragma unroll
            for (int mt = 0; mt < 2; ++mt) {
                float dA = __ldg(&dk[m0 + mt * 16 + g]);
                float dB = __ldg(&dk[m0 + mt * 16 + 8 + g]);
                #pragma unroll
                for (int nt = 0; nt < 4; ++nt) {
                    h[mt][nt][0] = dA * h[mt][nt][0] + accU[mt][nt][0];
                    h[mt][nt][1] = dA * h[mt][nt][1] + accU[mt][nt][1];
                    h[mt][nt][2] = dB * h[mt][nt][2] + accU[mt][nt][2];
                    h[mt][nt][3] = dB * h[mt][nt][3] + accU[mt][nt][3];
                }
            }
        }

        // ---- h-write h(t+1) -> Hnxt ----
        #pragma unroll
        for (int mt = 0; mt < 2; ++mt)
            #pragma unroll
            for (int nt = 0; nt < 4; ++nt) {
                int c_lo = m0 + mt * 16 + g;
                int cb   = (n0 + nt * 8 + tq * 2) * 2;
                *(uint32_t*)(hnxt - sb + smem + (uint32_t)(c_lo * ROWB + cb)) =
                    pack_h2(h[mt][nt][0], h[mt][nt][1]);
                *(uint32_t*)(hnxt - sb + smem + (uint32_t)((c_lo + 8) * ROWB + cb)) =
                    pack_h2(h[mt][nt][2], h[mt][nt][3]);
            }

        // ---- residual accR = x(t+1) from Xnxt ----
        #pragma unroll
        for (int mt = 0; mt < 2; ++mt)
            #pragma unroll
            for (int nt = 0; nt < 4; ++nt) {
                int c_lo = m0 + mt * 16 + g;
                int cb   = (n0 + nt * 8 + tq * 2) * 2;
                float2 r0 = unpack_h2(*(const uint32_t*)(xnxt - sb + smem + (uint32_t)(c_lo * ROWB + cb)));
                float2 r1 = unpack_h2(*(const uint32_t*)(xnxt - sb + smem + (uint32_t)((c_lo + 8) * ROWB + cb)));
                accR[mt][nt][0] = r0.x; accR[mt][nt][1] = r0.y;
                accR[mt][nt][2] = r1.x; accR[mt][nt][3] = r1.y;
            }

        // ---- stage x(t+2) -> Xstg; prefetch x(t+3) ----
        #pragma unroll
        for (int it = 0; it < 8; ++it) {
            int r = it * 16 + sr;
            float4 v = xr[it];
            *(uint2*)(xstg - sb + smem + (uint32_t)(r * ROWB + sc4 * 8)) =
                make_uint2(pack_h2(v.x, v.y), pack_h2(v.z, v.w));
        }
        {
            int tn = (t + 3 < L_DIM) ? t + 3 : L_DIM - 1;
            #pragma unroll
            for (int it = 0; it < 8; ++it) {
                int r = it * 16 + sr;
                xr[it] = *(const float4*)(x + ((size_t)(b * C_DIM + r) * L_DIM + tn) * HW_DIM
                                            + s0 + sc4 * 4);
            }
        }
        __syncthreads();   // single barrier per region
    }

    // ---- final step t = L-1: gemm2 + store only ----
    {
        const int t = L_DIM - 1;
        const uint32_t hcur = sb + (uint32_t)((t & 1) ? SM_H1 : SM_H0);
        gemm128(sb + SM_W, hcur, m0, n0, lane, accR);
        #pragma unroll
        for (int mt = 0; mt < 2; ++mt)
            #pragma unroll
            for (int nt = 0; nt < 4; ++nt) {
                int d_lo = m0 + mt * 16 + g;
                float* po = out + ((size_t)(b * C_DIM + d_lo) * L_DIM + t) * HW_DIM
                                + s0 + n0 + nt * 8 + tq * 2;
                *(float2*)po = make_float2(accR[mt][nt][0], accR[mt][nt][1]);
                *(float2*)(po + 8 * rstride) = make_float2(accR[mt][nt][2], accR[mt][nt][3]);
            }
    }

    // ---- final hidden state h(L-1) ----
    #pragma unroll
    for (int mt = 0; mt < 2; ++mt) {
        #pragma unroll
        for (int nt = 0; nt < 4; ++nt) {
            int c_lo = m0 + mt * 16 + g;
            int s    = s0 + n0 + nt * 8 + tq * 2;
            *(float2*)&hfin[(size_t)(b * C_DIM + c_lo) * HW_DIM + s] =
                make_float2(h[mt][nt][0], h[mt][nt][1]);
            *(float2*)&hfin[(size_t)(b * C_DIM + c_lo + 8) * HW_DIM + s] =
                make_float2(h[mt][nt][2], h[mt][nt][3]);
        }
    }
}

extern "C" void kernel_launch(void* const* d_in, const int* in_sizes, int n_in,
                              void* d_out, int out_size) {
    const float* x     = (const float*)d_in[0];
    const float* h0    = (const float*)d_in[1];
    const float* listT = (const float*)d_in[2];
    const float* lam   = (const float*)d_in[3];
    const float* U     = (const float*)d_in[4];
    const float* V     = (const float*)d_in[5];
    const float* Wout  = (const float*)d_in[6];

    float* out  = (float*)d_out;
    float* hfin = out + (size_t)B_DIM * C_DIM * L_DIM * HW_DIM;

    precompute_kernel<<<112, 256>>>(lam, U, V, listT);

    cudaFuncSetAttribute(recurrent_kernel,
                         cudaFuncAttributeMaxDynamicSharedMemorySize, SMEM_BYTES);
    recurrent_kernel<<<B_DIM * (HW_DIM / 128), NTHREADS, SMEM_BYTES>>>(x, h0, Wout, out, hfin);
}

// round 14
// speedup vs baseline: 1.0965x; 1.0965x over previous
#include <cuda_runtime.h>
#include <cuda_fp16.h>
#include <cstdint>

#define B_DIM 4
#define C_DIM 128
#define L_DIM 24
#define HW_DIM 4096

#define SK   136          // fp16 row stride in elements
#define ROWB (SK * 2)     // 272 bytes/row

#define SM_M   0
#define SM_W   34816
#define SM_BX  69632
#define SM_BH0 104448
#define SM_BH1 139264
#define SMEM_BYTES 174080

#define NTHREADS 256

__device__ __align__(16) float g_M[C_DIM * C_DIM];             // (U@V)[c][k]
__device__ __align__(16) float g_decay[B_DIM * L_DIM * C_DIM]; // exp(-softplus(lam)*dt)

// ---------------- helpers ----------------
__device__ __forceinline__ uint32_t smem_u32(const void* p) {
    uint32_t a;
    asm("{ .reg .u64 t; cvta.to.shared.u64 t, %1; cvt.u32.u64 %0, t; }" : "=r"(a) : "l"(p));
    return a;
}
__device__ __forceinline__ void ldsm4(uint32_t* r, uint32_t a) {
    asm volatile("ldmatrix.sync.aligned.m8n8.x4.shared.b16 {%0,%1,%2,%3}, [%4];"
                 : "=r"(r[0]), "=r"(r[1]), "=r"(r[2]), "=r"(r[3]) : "r"(a));
}
__device__ __forceinline__ void ldsm4t(uint32_t* r, uint32_t a) {
    asm volatile("ldmatrix.sync.aligned.m8n8.x4.trans.shared.b16 {%0,%1,%2,%3}, [%4];"
                 : "=r"(r[0]), "=r"(r[1]), "=r"(r[2]), "=r"(r[3]) : "r"(a));
}
__device__ __forceinline__ void mma16816(float* d, const uint32_t* a, const uint32_t* b) {
    asm volatile("mma.sync.aligned.m16n8k16.row.col.f32.f16.f16.f32 "
                 "{%0,%1,%2,%3}, {%4,%5,%6,%7}, {%8,%9}, {%0,%1,%2,%3};"
                 : "+f"(d[0]), "+f"(d[1]), "+f"(d[2]), "+f"(d[3])
                 : "r"(a[0]), "r"(a[1]), "r"(a[2]), "r"(a[3]), "r"(b[0]), "r"(b[1]));
}
__device__ __forceinline__ uint32_t pack_h2(float x0, float x1) {
    uint32_t r;
    asm("cvt.rn.f16x2.f32 %0, %1, %2;" : "=r"(r) : "f"(x1), "f"(x0));
    return r;
}
__device__ __forceinline__ float2 unpack_h2(uint32_t v) {
    return __half22float2(*reinterpret_cast<__half2*>(&v));
}

// ---------------- precompute ----------------
__global__ void precompute_kernel(const float* __restrict__ lam,
                                  const float* __restrict__ U,
                                  const float* __restrict__ V,
                                  const float* __restrict__ listT) {
    int tid = threadIdx.x;
    if (blockIdx.x < 64) {
        int e = blockIdx.x * 256 + tid;
        int c = e >> 7, k = e & 127;
        float s0 = 0.f, s1 = 0.f;
        #pragma unroll 8
        for (int r = 0; r < 64; r += 2) {
            s0 += U[c * 64 + r] * V[r * C_DIM + k];
            s1 += U[c * 64 + r + 1] * V[(r + 1) * C_DIM + k];
        }
        g_M[e] = s0 + s1;
    } else {
        int idx = (blockIdx.x - 64) * 256 + tid;
        if (idx < B_DIM * L_DIM * C_DIM) {
            int c = idx & 127;
            int t = (idx >> 7) % L_DIM;
            int b = idx / (L_DIM * C_DIM);
            float sp = log1pf(expf(lam[c]));
            g_decay[idx] = expf(-sp * listT[b * L_DIM + t]);
        }
    }
}

// single-pass fp16 GEMM, k=128: acc[2][8][4] += A[m0..+32][k] * B[k][n0..+64]
__device__ __forceinline__ void gemm128(uint32_t aB, uint32_t bB,
                                        int m0, int n0, int lane,
                                        float acc[2][8][4]) {
    const int arow = lane & 15;
    const int aq   = lane >> 4;
    #pragma unroll
    for (int k = 0; k < 128; k += 16) {
        uint32_t ah[2][4];
        #pragma unroll
        for (int mt = 0; mt < 2; ++mt) {
            uint32_t addr = aB + (uint32_t)((m0 + mt * 16 + arow) * ROWB + k * 2 + aq * 16);
            ldsm4(ah[mt], addr);
        }
        #pragma unroll
        for (int ng = 0; ng < 4; ++ng) {
            uint32_t addr = bB + (uint32_t)((k + arow) * ROWB + (n0 + ng * 16) * 2 + aq * 16);
            uint32_t bv[4];
            ldsm4t(bv, addr);
            #pragma unroll
            for (int hh = 0; hh < 2; ++hh) {
                const int nt = ng * 2 + hh;
                mma16816(acc[0][nt], ah[0], bv + hh * 2);
                mma16816(acc[1][nt], ah[1], bv + hh * 2);
            }
        }
    }
}

// ---------------- main kernel ----------------
__global__ __launch_bounds__(NTHREADS, 1)
void recurrent_kernel(const float* __restrict__ x,
                      const float* __restrict__ h0,
                      const float* __restrict__ Wout,
                      float* __restrict__ out,
                      float* __restrict__ hfin) {
    extern __shared__ char smem[];
    const uint32_t sb = smem_u32(smem);

    const int tid  = threadIdx.x;
    const int lane = tid & 31;
    const int wid  = tid >> 5;            // 0..7
    const int b    = blockIdx.x >> 5;
    const int s0   = (blockIdx.x & 31) * 128;
    const int wm   = wid & 3;
    const int wn   = wid >> 2;            // 0..1
    const int m0   = wm * 32;
    const int n0   = wn * 64;
    const int g    = lane >> 2;
    const int tq   = lane & 3;
    const size_t rstride = (size_t)L_DIM * HW_DIM;

    const int sr  = tid >> 5;       // staging base row (0..7, stride 8)
    const int sc4 = tid & 31;       // float4 column (0..31)

    // ---- stationary weights (fp16) ----
    for (int e = tid; e < C_DIM * C_DIM; e += NTHREADS) {
        int r = e >> 7, k = e & 127;
        uint32_t off = (uint32_t)(r * ROWB + k * 2);
        *(__half*)(smem + SM_M + off) = __float2half_rn(g_M[e]);
        *(__half*)(smem + SM_W + off) = __float2half_rn(Wout[e]);
    }

    // ---- initial hidden state fragments ----
    float h[2][8][4];
    #pragma unroll
    for (int mt = 0; mt < 2; ++mt) {
        #pragma unroll
        for (int nt = 0; nt < 8; ++nt) {
            int c_lo = m0 + mt * 16 + g;
            int s    = s0 + n0 + nt * 8 + tq * 2;
            float2 v0 = *(const float2*)&h0[(size_t)(b * C_DIM + c_lo) * HW_DIM + s];
            float2 v1 = *(const float2*)&h0[(size_t)(b * C_DIM + c_lo + 8) * HW_DIM + s];
            h[mt][nt][0] = v0.x; h[mt][nt][1] = v0.y;
            h[mt][nt][2] = v1.x; h[mt][nt][3] = v1.y;
        }
    }

    // ---- pre-loop: stage x(0) into BX directly; prefetch x(1) ----
    #pragma unroll
    for (int it = 0; it < 16; ++it) {
        int r = it * 8 + sr;
        float4 v = *(const float4*)(x + ((size_t)(b * C_DIM + r) * L_DIM + 0) * HW_DIM
                                      + s0 + sc4 * 4);
        *(uint2*)(smem + SM_BX + (uint32_t)(r * ROWB + sc4 * 8)) =
            make_uint2(pack_h2(v.x, v.y), pack_h2(v.z, v.w));
    }
    float4 xr[16];
    #pragma unroll
    for (int it = 0; it < 16; ++it) {
        int r = it * 8 + sr;
        xr[it] = *(const float4*)(x + ((size_t)(b * C_DIM + r) * L_DIM + 1) * HW_DIM
                                    + s0 + sc4 * 4);
    }

    for (int t = 0; t < L_DIM; ++t) {
        const uint32_t bh = sb + (uint32_t)((t & 1) ? SM_BH1 : SM_BH0);

        __syncthreads();   // BAR1: BX(x(t)) staged; weights ready (t=0)

        // ---- GEMM1: u = M @ x(t) ----
        float acc[2][8][4];
        #pragma unroll
        for (int mt = 0; mt < 2; ++mt)
            #pragma unroll
            for (int nt = 0; nt < 8; ++nt)
                #pragma unroll
                for (int q = 0; q < 4; ++q) acc[mt][nt][q] = 0.f;
        gemm128(sb + SM_M, sb + SM_BX, m0, n0, lane, acc);

        // ---- recurrence: h = decay(c)*h + u ----
        {
            const float* dk = &g_decay[(b * L_DIM + t) * C_DIM];
            #pragma unroll
            for (int mt = 0; mt < 2; ++mt) {
                float dA = __ldg(&dk[m0 + mt * 16 + g]);
                float dB = __ldg(&dk[m0 + mt * 16 + 8 + g]);
                #pragma unroll
                for (int nt = 0; nt < 8; ++nt) {
                    h[mt][nt][0] = dA * h[mt][nt][0] + acc[mt][nt][0];
                    h[mt][nt][1] = dA * h[mt][nt][1] + acc[mt][nt][1];
                    h[mt][nt][2] = dB * h[mt][nt][2] + acc[mt][nt][2];
                    h[mt][nt][3] = dB * h[mt][nt][3] + acc[mt][nt][3];
                }
            }
        }

        // ---- residual x(t) from BX (fp16 hi-only) into GEMM2 accumulators ----
        #pragma unroll
        for (int mt = 0; mt < 2; ++mt) {
            #pragma unroll
            for (int nt = 0; nt < 8; ++nt) {
                int c_lo = m0 + mt * 16 + g;
                int cb   = (n0 + nt * 8 + tq * 2) * 2;
                float2 r0 = unpack_h2(*(const uint32_t*)(smem + SM_BX + (uint32_t)(c_lo * ROWB + cb)));
                float2 r1 = unpack_h2(*(const uint32_t*)(smem + SM_BX + (uint32_t)((c_lo + 8) * ROWB + cb)));
                acc[mt][nt][0] = r0.x; acc[mt][nt][1] = r0.y;
                acc[mt][nt][2] = r1.x; acc[mt][nt][3] = r1.y;
            }
        }

        // ---- write h (f16) into BH_cur ----
        #pragma unroll
        for (int mt = 0; mt < 2; ++mt) {
            #pragma unroll
            for (int nt = 0; nt < 8; ++nt) {
                int c_lo = m0 + mt * 16 + g;
                int cb   = (n0 + nt * 8 + tq * 2) * 2;
                *(uint32_t*)(bh - sb + smem + (uint32_t)(c_lo * ROWB + cb)) =
                    pack_h2(h[mt][nt][0], h[mt][nt][1]);
                *(uint32_t*)(bh - sb + smem + (uint32_t)((c_lo + 8) * ROWB + cb)) =
                    pack_h2(h[mt][nt][2], h[mt][nt][3]);
            }
        }
        __syncthreads();   // BAR2 (mid): BH_cur visible; all BX reads complete

        // ---- stage x(t+1) into BX (safe: all readers past BAR2); prefetch x(t+2) ----
        #pragma unroll
        for (int it = 0; it < 16; ++it) {
            int r = it * 8 + sr;
            float4 v = xr[it];
            *(uint2*)(smem + SM_BX + (uint32_t)(r * ROWB + sc4 * 8)) =
                make_uint2(pack_h2(v.x, v.y), pack_h2(v.z, v.w));
        }
        {
            int tn = (t + 2 < L_DIM) ? t + 2 : L_DIM - 1;
            #pragma unroll
            for (int it = 0; it < 16; ++it) {
                int r = it * 8 + sr;
                xr[it] = *(const float4*)(x + ((size_t)(b * C_DIM + r) * L_DIM + tn) * HW_DIM
                                            + s0 + sc4 * 4);
            }
        }

        // ---- GEMM2: out = x + Wout @ h(t) ----
        gemm128(sb + SM_W, bh, m0, n0, lane, acc);

        // ---- store output ----
        #pragma unroll
        for (int mt = 0; mt < 2; ++mt) {
            #pragma unroll
            for (int nt = 0; nt < 8; ++nt) {
                int d_lo = m0 + mt * 16 + g;
                float* po = out + ((size_t)(b * C_DIM + d_lo) * L_DIM + t) * HW_DIM
                                + s0 + n0 + nt * 8 + tq * 2;
                *(float2*)po = make_float2(acc[mt][nt][0], acc[mt][nt][1]);
                *(float2*)(po + 8 * rstride) = make_float2(acc[mt][nt][2], acc[mt][nt][3]);
            }
        }
        // no trailing barrier: next BAR1 protects BX (staged above) and BH_alt.
    }

    // ---- final hidden state ----
    #pragma unroll
    for (int mt = 0; mt < 2; ++mt) {
        #pragma unroll
        for (int nt = 0; nt < 8; ++nt) {
            int c_lo = m0 + mt * 16 + g;
            int s    = s0 + n0 + nt * 8 + tq * 2;
            *(float2*)&hfin[(size_t)(b * C_DIM + c_lo) * HW_DIM + s] =
                make_float2(h[mt][nt][0], h[mt][nt][1]);
            *(float2*)&hfin[(size_t)(b * C_DIM + c_lo + 8) * HW_DIM + s] =
                make_float2(h[mt][nt][2], h[mt][nt][3]);
        }
    }
}

extern "C" void kernel_launch(void* const* d_in, const int* in_sizes, int n_in,
                              void* d_out, int out_size) {
    const float* x     = (const float*)d_in[0];
    const float* h0    = (const float*)d_in[1];
    const float* listT = (const float*)d_in[2];
    const float* lam   = (const float*)d_in[3];
    const float* U     = (const float*)d_in[4];
    const float* V     = (const float*)d_in[5];
    const float* Wout  = (const float*)d_in[6];

    float* out  = (float*)d_out;
    float* hfin = out + (size_t)B_DIM * C_DIM * L_DIM * HW_DIM;

    precompute_kernel<<<112, 256>>>(lam, U, V, listT);

    cudaFuncSetAttribute(recurrent_kernel,
                         cudaFuncAttributeMaxDynamicSharedMemorySize, SMEM_BYTES);
    recurrent_kernel<<<B_DIM * (HW_DIM / 128), NTHREADS, SMEM_BYTES>>>(x, h0, Wout, out, hfin);
}